// round 17
// baseline (speedup 1.0000x reference)
#include <cuda_runtime.h>
#include <cuda_fp16.h>
#include <cstdint>

#define SDIM 2048
#define BDIM 16
#define DDIM 64
#define DVDIM 512
#define QB 32
#define JT 64
#define NT 512

// ---------------- scratch ---------------------------------------------------
__device__ __half g_Kth[DDIM * SDIM];    // fp16 hi of (m@n^T)/64, [d][s]
__device__ __half g_Ktl[DDIM * SDIM];    // fp16 lo residual
__device__ __half g_Vh[SDIM * DVDIM];    // V fp16, [j][dv]

// ---------------- helpers ---------------------------------------------------
#define CPA16(dst, src)  asm volatile("cp.async.cg.shared.global [%0], [%1], 16;" :: "r"(dst), "l"(src))
#define CPA_COMMIT()     asm volatile("cp.async.commit_group;")
#define CPA_WAIT0()      asm volatile("cp.async.wait_group 0;")
#define CPA_WAIT1()      asm volatile("cp.async.wait_group 1;")

__device__ __forceinline__ uint32_t smem_u32(const void* p) {
    uint32_t a;
    asm("{ .reg .u64 t; cvta.to.shared.u64 t, %1; cvt.u32.u64 %0, t; }" : "=r"(a) : "l"(p));
    return a;
}
__device__ __forceinline__ void bar_sync(int id, int cnt) {
    asm volatile("bar.sync %0, %1;" :: "r"(id), "r"(cnt) : "memory");
}
__device__ __forceinline__ void bar_arrive(int id, int cnt) {
    asm volatile("bar.arrive %0, %1;" :: "r"(id), "r"(cnt) : "memory");
}
__device__ __forceinline__ void ldsm4(uint32_t* r, uint32_t addr) {
    asm volatile("ldmatrix.sync.aligned.m8n8.x4.shared.b16 {%0,%1,%2,%3}, [%4];"
        : "=r"(r[0]), "=r"(r[1]), "=r"(r[2]), "=r"(r[3]) : "r"(addr));
}
__device__ __forceinline__ void ldsm4t(uint32_t* r, uint32_t addr) {
    asm volatile("ldmatrix.sync.aligned.m8n8.x4.trans.shared.b16 {%0,%1,%2,%3}, [%4];"
        : "=r"(r[0]), "=r"(r[1]), "=r"(r[2]), "=r"(r[3]) : "r"(addr));
}
__device__ __forceinline__ void mma16(float* c, const uint32_t* a, uint32_t b0, uint32_t b1) {
    asm volatile("mma.sync.aligned.m16n8k16.row.col.f32.f16.f16.f32 "
        "{%0,%1,%2,%3}, {%4,%5,%6,%7}, {%8,%9}, {%0,%1,%2,%3};"
        : "+f"(c[0]), "+f"(c[1]), "+f"(c[2]), "+f"(c[3])
        : "r"(a[0]), "r"(a[1]), "r"(a[2]), "r"(a[3]), "r"(b0), "r"(b1));
}

// ---------------- threefry2x32, key=(0,42), partitionable ------------------
__device__ __forceinline__ uint2 tf2x32(uint32_t x0, uint32_t x1) {
    const uint32_t K1 = 42u;
    const uint32_t K2 = 0x1BD11BDAu ^ 42u;
#define TFR(r) { x0 += x1; x1 = __funnelshift_l(x1, x1, (r)); x1 ^= x0; }
    x1 += K1;
    TFR(13) TFR(15) TFR(26) TFR(6)
    x0 += K1; x1 += K2 + 1u;
    TFR(17) TFR(29) TFR(16) TFR(24)
    x0 += K2; x1 += 0u + 2u;
    TFR(13) TFR(15) TFR(26) TFR(6)
    x1 += K1 + 3u;
    TFR(17) TFR(29) TFR(16) TFR(24)
    x0 += K1; x1 += K2 + 4u;
    TFR(13) TFR(15) TFR(26) TFR(6)
    x0 += K2; x1 += 0u + 5u;
#undef TFR
    return make_uint2(x0, x1);
}
// keep iff u < 0.75  ⟺  (x^y) < 0xC0000000  (exact integer equivalent)
__device__ __forceinline__ bool keep_mask(uint32_t f) {
    uint2 r = tf2x32(0u, f);
    return (r.x ^ r.y) < 0xC0000000u;
}
// pack 8 consecutive-col mask bits into one byte (bit k = col offset k)
__device__ __forceinline__ void gen_mask8(uint8_t* dst, uint32_t fb) {
    uint32_t by = 0;
#pragma unroll
    for (int k = 0; k < 8; ++k)
        by |= (uint32_t)keep_mask(fb + (uint32_t)k) << k;
    *dst = (uint8_t)by;
}

// ---------------------------------------------------------------------------
// Kernel 1: K' = (m @ n^T)/64, fp16 hi/lo. grid 256 (s-blocks of 8), 256 thr.
//   2 accumulators/thread (more blocks -> better latency hiding). swizzled smm.
// ---------------------------------------------------------------------------
__global__ __launch_bounds__(256) void k_build_kt(
    const float* __restrict__ m, const float* __restrict__ n) {
    __shared__ float smm[64][64];
    __shared__ float snn[8][68];
    const int t = threadIdx.x;
    const int s0 = blockIdx.x * 8;
    const int di = (t & 31) * 2, sj = t >> 5;
    float acc[2] = {};
    for (int c0 = 0; c0 < DVDIM; c0 += 64) {
#pragma unroll
        for (int u = 0; u < 4; ++u) {
            int idx = t + u * 256;
            int r = idx >> 4, c4 = (idx & 15) * 4;
            float4 v = *reinterpret_cast<const float4*>(m + (size_t)r * DVDIM + c0 + c4);
            smm[r][(c4 + 0 + r) & 63] = v.x;
            smm[r][(c4 + 1 + r) & 63] = v.y;
            smm[r][(c4 + 2 + r) & 63] = v.z;
            smm[r][(c4 + 3 + r) & 63] = v.w;
        }
        if (t < 128) {
            int r = t >> 4, c4 = (t & 15) * 4;
            *reinterpret_cast<float4*>(&snn[r][c4]) =
                *reinterpret_cast<const float4*>(n + (size_t)(s0 + r) * DVDIM + c0 + c4);
        }
        __syncthreads();
#pragma unroll 16
        for (int c = 0; c < 64; ++c) {
            float nv = snn[sj][c];
            acc[0] += smm[di + 0][(c + di + 0) & 63] * nv;
            acc[1] += smm[di + 1][(c + di + 1) & 63] * nv;
        }
        __syncthreads();
    }
#pragma unroll
    for (int i = 0; i < 2; ++i) {
        float val = acc[i] * (1.0f / 64.0f);
        __half hh = __float2half_rn(val);
        g_Kth[(size_t)(di + i) * SDIM + s0 + sj] = hh;
        g_Ktl[(size_t)(di + i) * SDIM + s0 + sj] = __float2half_rn(val - __half2float(hh));
    }
}

// ---------------------------------------------------------------------------
// Kernel 2: g_Vh = fp16(q)
// ---------------------------------------------------------------------------
__global__ void k_vr(const float* __restrict__ q) {
    const int idx = blockIdx.x * 256 + threadIdx.x;
    float4 v = reinterpret_cast<const float4*>(q)[idx];
    __half2* dst = reinterpret_cast<__half2*>(g_Vh) + idx * 2;
    dst[0] = __floats2half2_rn(v.x, v.y);
    dst[1] = __floats2half2_rn(v.z, v.w);
}

// ---------------------------------------------------------------------------
// Kernel 3: warp-specialized fused attention, masks generated by consumers.
//   Warps 0-7 (producers): K cp.async, QK mma, exp, P write (reads mask bits).
//   Warps 8-15 (consumers): V cp.async, PV mma, threefry masks for tile i+2.
//   QB=32, JT=64, 32 tiles, grid 1024, 512 threads.
// Named barriers: 1 prod-internal, 2 cons-internal,
//                 3+bf full[bf] (prod arrive / cons sync),
//                 5+bf empty[bf] (cons arrive / prod sync; also: mask(i) ready).
// smem (bytes):
//   LF 0 (128)  LP 128 (512)
//   MB bufs 640: 2 x 256 (mask bits: byte = (row, colgroup8))
//   QH 1152 (4608)  QL 5760 (4608)
//   K bufs 10368: 2 x {KH 9216, KL 9216} = 36864
//   P bufs 47232: 2 x 4608
//   V bufs 56448: 2 x 66560       total 189568
// ---------------------------------------------------------------------------
#define OFF_LF 0
#define OFF_LP 128
#define OFF_MB(bf) (640 + (bf) * 256)
#define OFF_QH 1152
#define OFF_QL 5760
#define OFF_KH(bf) (10368 + (bf) * 18432)
#define OFF_KL(bf) (10368 + (bf) * 18432 + 9216)
#define OFF_P(bf)  (47232 + (bf) * 4608)
#define OFF_V(bf)  (56448 + (bf) * 66560)
#define ATT_SMEM 189568
#define QSTRB 144
#define KSTRB 144
#define PSTRH 72
#define VSTRB 1040
#define P_SC 6.103515625e-05f   // 2^-14
#define P_UNSC 16384.0f
#define NTILE 32

__device__ __forceinline__ void issueK(uint32_t sb, int bf, int j0, int tp) {
#pragma unroll
    for (int u = 0; u < 2; ++u) {
        int idx = tp + u * 256;
        int d = idx >> 3, c = idx & 7;
        uint32_t dsto = (uint32_t)(d * KSTRB + c * 16);
        CPA16(sb + OFF_KH(bf) + dsto, g_Kth + (size_t)d * SDIM + j0 + c * 8);
        CPA16(sb + OFF_KL(bf) + dsto, g_Ktl + (size_t)d * SDIM + j0 + c * 8);
    }
}
__device__ __forceinline__ void issueV(uint32_t sb, int bf, int j0, int tc) {
#pragma unroll
    for (int u = 0; u < 16; ++u) {
        int idx = tc + u * 256;
        int jr = idx >> 6, c = idx & 63;
        CPA16(sb + OFF_V(bf) + (uint32_t)(jr * VSTRB + c * 16),
              g_Vh + (size_t)(j0 + jr) * DVDIM + c * 8);
    }
}

__global__ __launch_bounds__(NT, 1) void k_attn(
    const float* __restrict__ x1, float* __restrict__ out) {
    extern __shared__ char smem[];
    const uint32_t sb = smem_u32(smem);
    float* lf    = reinterpret_cast<float*>(smem + OFF_LF);
    float* lpart = reinterpret_cast<float*>(smem + OFF_LP);
    __half* sQh  = reinterpret_cast<__half*>(smem + OFF_QH);
    __half* sQl  = reinterpret_cast<__half*>(smem + OFF_QL);

    const int t = threadIdx.x, w = t >> 5, lane = t & 31;
    const int g = lane >> 2, tid = lane & 3;
    const int b = blockIdx.x >> 6;
    const int i0 = (blockIdx.x & 63) << 5;
    const int lrow = lane & 15;
    const int lcol8 = (lane >> 4) * 8;

    if (t < 128) lpart[t] = 0.f;

    // ---- all threads: load Q (32 x 64), split fp16 hi/lo ----
    {
        const float* xq = x1 + ((size_t)b * SDIM + i0) * DDIM;
        int r = t >> 4, d4 = (t & 15) << 2;
        float4 v = *reinterpret_cast<const float4*>(xq + (size_t)r * DDIM + d4);
        __half hx = __float2half_rn(v.x), hy = __float2half_rn(v.y);
        __half hz = __float2half_rn(v.z), hw = __float2half_rn(v.w);
        __half lx = __float2half_rn(v.x - __half2float(hx));
        __half ly = __float2half_rn(v.y - __half2float(hy));
        __half lz = __float2half_rn(v.z - __half2float(hz));
        __half lw = __float2half_rn(v.w - __half2float(hw));
        *reinterpret_cast<__half2*>(sQh + r * PSTRH + d4)     = __halves2half2(hx, hy);
        *reinterpret_cast<__half2*>(sQh + r * PSTRH + d4 + 2) = __halves2half2(hz, hw);
        *reinterpret_cast<__half2*>(sQl + r * PSTRH + d4)     = __halves2half2(lx, ly);
        *reinterpret_cast<__half2*>(sQl + r * PSTRH + d4 + 2) = __halves2half2(lz, lw);
    }
    __syncthreads();

    // ---- consumers: prologue mask gen for tiles 0 and 1 ----
    if (w >= 8) {
        const int tc = t - 256;
        const int mrow = tc >> 3, mcg = tc & 7;
        const uint32_t fbm = ((uint32_t)b << 22) | ((uint32_t)(i0 + mrow) << 11)
                           | (uint32_t)(mcg * 8);
        gen_mask8(reinterpret_cast<uint8_t*>(smem + OFF_MB(0)) + mrow * 8 + mcg, fbm);
        gen_mask8(reinterpret_cast<uint8_t*>(smem + OFF_MB(1)) + mrow * 8 + mcg, fbm + JT);
    }
    __syncthreads();          // masks 0,1 visible to producers

    if (w < 8) {
        // =================== PRODUCERS (warps 0-7) ==========================
        const int tp = t;
        const int m0 = (w & 1) * 16;
        const int n0 = (w >> 1) * 16;
        const int wc = w >> 1;
        const float psc = (1.0f / 0.75f) * P_SC;

        issueK(sb, 0, 0, tp);
        CPA_COMMIT();

        for (int i = 0; i < NTILE; ++i) {
            const int bf = i & 1;
            if (i < NTILE - 1) { issueK(sb, bf ^ 1, (i + 1) * JT, tp); CPA_COMMIT(); }
            if (i < NTILE - 1) CPA_WAIT1(); else CPA_WAIT0();
            bar_sync(1, 256);                     // K(i) visible to producers

            // ---- QK: fp16 split (hh + hl + lh) ----
            float cfr[2][4] = {{0.f, 0.f, 0.f, 0.f}, {0.f, 0.f, 0.f, 0.f}};
#pragma unroll
            for (int ks = 0; ks < 4; ++ks) {
                const int k0 = ks * 16;
                uint32_t ah[4], al[4], bh[4], bl[4];
                uint32_t qoff = (uint32_t)((m0 + lrow) * QSTRB + (k0 + lcol8) * 2);
                ldsm4(ah, sb + OFF_QH + qoff);
                ldsm4(al, sb + OFF_QL + qoff);
                uint32_t koff = (uint32_t)((k0 + lrow) * KSTRB + (n0 + lcol8) * 2);
                ldsm4t(bh, sb + OFF_KH(bf) + koff);
                ldsm4t(bl, sb + OFF_KL(bf) + koff);
#pragma unroll
                for (int u = 0; u < 2; ++u) {
                    mma16(cfr[u], ah, bh[u * 2], bh[u * 2 + 1]);
                    mma16(cfr[u], ah, bl[u * 2], bl[u * 2 + 1]);
                    mma16(cfr[u], al, bh[u * 2], bh[u * 2 + 1]);
                }
            }

            // ---- exp + l partials ----
            float pe[2][4];
            float lg = 0.f, lg8 = 0.f;
#pragma unroll
            for (int u = 0; u < 2; ++u) {
                pe[u][0] = __expf(cfr[u][0]);
                pe[u][1] = __expf(cfr[u][1]);
                pe[u][2] = __expf(cfr[u][2]);
                pe[u][3] = __expf(cfr[u][3]);
                lg += pe[u][0] + pe[u][1];
                lg8 += pe[u][2] + pe[u][3];
            }
            lg  += __shfl_xor_sync(0xffffffffu, lg, 1);
            lg  += __shfl_xor_sync(0xffffffffu, lg, 2);
            lg8 += __shfl_xor_sync(0xffffffffu, lg8, 1);
            lg8 += __shfl_xor_sync(0xffffffffu, lg8, 2);
            if (tid == 0) {
                lpart[wc * 32 + m0 + g]     += lg;
                lpart[wc * 32 + m0 + 8 + g] += lg8;
            }

            if (i >= 2) bar_sync(5 + bf, 512);    // empty[bf]: P(i-2) consumed
                                                  //   AND mask(i) written

            // ---- apply consumer-generated mask bits, write P ----
            const uint8_t* mb = reinterpret_cast<const uint8_t*>(smem + OFF_MB(bf));
            uint32_t mlo = *reinterpret_cast<const uint16_t*>(mb + (m0 + g) * 8 + (n0 >> 3));
            uint32_t mhi = *reinterpret_cast<const uint16_t*>(mb + (m0 + g + 8) * 8 + (n0 >> 3));
            __half* sP = reinterpret_cast<__half*>(smem + OFF_P(bf));
#pragma unroll
            for (int u = 0; u < 2; ++u) {
                const int c0 = u * 8 + 2 * tid;
                float v0 = ((mlo >> c0) & 1u)       ? pe[u][0] * psc : 0.f;
                float v1 = ((mlo >> (c0 + 1)) & 1u) ? pe[u][1] * psc : 0.f;
                float v2 = ((mhi >> c0) & 1u)       ? pe[u][2] * psc : 0.f;
                float v3 = ((mhi >> (c0 + 1)) & 1u) ? pe[u][3] * psc : 0.f;
                __half* pb = sP + (m0 + g) * PSTRH + n0 + u * 8 + 2 * tid;
                *reinterpret_cast<__half2*>(pb)             = __floats2half2_rn(v0, v1);
                *reinterpret_cast<__half2*>(pb + 8 * PSTRH) = __floats2half2_rn(v2, v3);
            }
            bar_arrive(3 + bf, 512);              // full[bf]: P(i) ready
            bar_sync(1, 256);
        }
    } else {
        // =================== CONSUMERS (warps 8-15) =========================
        const int tc = t - 256;
        const int cw = w - 8;
        const int colbase = cw * 64;
        const int mrow = tc >> 3, mcg = tc & 7;
        const uint32_t fbm = ((uint32_t)b << 22) | ((uint32_t)(i0 + mrow) << 11)
                           | (uint32_t)(mcg * 8);
        uint8_t* mbp[2] = {
            reinterpret_cast<uint8_t*>(smem + OFF_MB(0)) + mrow * 8 + mcg,
            reinterpret_cast<uint8_t*>(smem + OFF_MB(1)) + mrow * 8 + mcg };

        float acc[2][8][4];
#pragma unroll
        for (int rt = 0; rt < 2; ++rt)
#pragma unroll
            for (int ct = 0; ct < 8; ++ct)
#pragma unroll
                for (int k = 0; k < 4; ++k) acc[rt][ct][k] = 0.f;

        issueV(sb, 0, 0, tc);
        CPA_COMMIT();

        for (int i = 0; i < NTILE; ++i) {
            const int bf = i & 1;
            if (i < NTILE - 1) { issueV(sb, bf ^ 1, (i + 1) * JT, tc); CPA_COMMIT(); }
            if (i < NTILE - 1) CPA_WAIT1(); else CPA_WAIT0();
            bar_sync(2, 256);                     // V(i) visible to consumers
            bar_sync(3 + bf, 512);                // full[bf]: P(i) ready
                                                  //   (also: mask(i) no longer read)

            // ---- PV: O[32x512] += P[32x64] @ V[64x512] ----
#pragma unroll
            for (int ks = 0; ks < 4; ++ks) {
                const int k0 = ks * 16;
                uint32_t ap[2][4];
#pragma unroll
                for (int rt = 0; rt < 2; ++rt) {
                    uint32_t poff = (uint32_t)((rt * 16 + lrow) * (PSTRH * 2) + (k0 + lcol8) * 2);
                    ldsm4(ap[rt], sb + OFF_P(bf) + poff);
                }
#pragma unroll
                for (int grp = 0; grp < 4; ++grp) {
                    uint32_t bv[4];
                    uint32_t voff = (uint32_t)((k0 + lrow) * VSTRB +
                                               (colbase + grp * 16 + lcol8) * 2);
                    ldsm4t(bv, sb + OFF_V(bf) + voff);
#pragma unroll
                    for (int h = 0; h < 2; ++h) {
                        const int ct = grp * 2 + h;
#pragma unroll
                        for (int rt = 0; rt < 2; ++rt)
                            mma16(acc[rt][ct], ap[rt], bv[h * 2], bv[h * 2 + 1]);
                    }
                }
            }

            // ---- threefry masks for tile i+2 (overlaps tensor-pipe drain) ----
            if (i < NTILE - 2)
                gen_mask8(mbp[bf], fbm + (uint32_t)((i + 2) * JT));

            bar_arrive(5 + bf, 512);              // empty[bf]: P(i) consumed
                                                  //   + mask(i+2) ready
            bar_sync(2, 256);
        }

        __syncthreads();                          // join with producers
        __syncthreads();

        const float* lfv = lf;
#pragma unroll
        for (int rt = 0; rt < 2; ++rt) {
            const int r0 = rt * 16 + g;
            const float inv0 = P_UNSC / lfv[r0];
            const float inv1 = P_UNSC / lfv[r0 + 8];
            float* o0 = out + ((size_t)(b * SDIM + i0 + r0)) * DVDIM;
            float* o1 = out + ((size_t)(b * SDIM + i0 + r0 + 8)) * DVDIM;
#pragma unroll
            for (int ct = 0; ct < 8; ++ct) {
                const int c = colbase + ct * 8 + tid * 2;
                *reinterpret_cast<float2*>(o0 + c) =
                    make_float2(acc[rt][ct][0] * inv0, acc[rt][ct][1] * inv0);
                *reinterpret_cast<float2*>(o1 + c) =
                    make_float2(acc[rt][ct][2] * inv1, acc[rt][ct][3] * inv1);
            }
        }
        return;
    }

    // producers: join epilogue syncs (must match consumer __syncthreads calls)
    __syncthreads();
    if (t < 32) lf[t] = lpart[t] + lpart[32 + t] + lpart[64 + t] + lpart[96 + t];
    __syncthreads();
}

// ---------------------------------------------------------------------------
extern "C" void kernel_launch(void* const* d_in, const int* in_sizes, int n_in,
                              void* d_out, int out_size) {
    const float* x1 = (const float*)d_in[0];  // [16,2048,64]
    const float* m  = (const float*)d_in[1];  // [64,512]
    const float* n  = (const float*)d_in[2];  // [2048,512]
    const float* q  = (const float*)d_in[3];  // [2048,512]
    float* out = (float*)d_out;               // [16,2048,512]

    cudaFuncSetAttribute(k_attn, cudaFuncAttributeMaxDynamicSharedMemorySize, ATT_SMEM);

    k_build_kt<<<SDIM / 8, 256>>>(m, n);
    k_vr<<<SDIM * DVDIM / 1024, 256>>>(q);
    k_attn<<<BDIM * (SDIM / QB), NT, ATT_SMEM>>>(x1, out);
}